// round 4
// baseline (speedup 1.0000x reference)
#include <cuda_runtime.h>

// Problem constants (fixed shapes):
//   x:      (16, 256, 64, 64)  fp32
//   weight: (8, 256)           fp32
//   bias:   (8,)               fp32
//   out:    (16, 256, 128, 128) fp32
#define Bn  16
#define Cn  256
#define Hn  64
#define Wn  64
#define OYn 128
#define OXn 128
#define PLANE (Hn * Wn)        // 4096
#define PADW 65                // padded row stride (float4 elements)

// Per-output-pixel sampling coordinates (ix, iy). 16*128*128 float2 = 2 MB.
__device__ float2 g_coord[Bn * OYn * OXn];

// ---------------------------------------------------------------------------
// Stage 1: 1x1 conv (8 dots of length 256) + pixel shuffle + grid build.
// Block = one (b, h) row: 64 pixels x 4 channel-parts (64 ch each).
// ---------------------------------------------------------------------------
__global__ __launch_bounds__(256) void dysample_stage1(
    const float* __restrict__ x,
    const float* __restrict__ weight,
    const float* __restrict__ bias)
{
    __shared__ float wt[Cn * 8];          // transposed: wt[c*8+o]
    __shared__ float part[3][64][9];      // padded to 9 -> conflict-free

    for (int i = threadIdx.x; i < Cn * 8; i += 256)
        wt[(i & 255) * 8 + (i >> 8)] = weight[i];
    __syncthreads();

    int w     = threadIdx.x & 63;
    int cpart = threadIdx.x >> 6;         // 0..3
    int bh    = blockIdx.x;               // b*64 + h
    int b     = bh >> 6;
    int h     = bh & 63;

    const float* xb = x + ((size_t)b * Cn + cpart * 64) * PLANE + h * Wn + w;
    const float* wr0 = &wt[(cpart * 64) * 8];

    float acc[8];
#pragma unroll
    for (int s = 0; s < 8; s++) acc[s] = 0.0f;

#pragma unroll 8
    for (int c = 0; c < 64; ++c) {
        float xv = __ldg(xb + (size_t)c * PLANE);       // coalesced along w
        float4 wa = *reinterpret_cast<const float4*>(wr0 + c * 8);
        float4 wb = *reinterpret_cast<const float4*>(wr0 + c * 8 + 4);
        acc[0] = fmaf(xv, wa.x, acc[0]);
        acc[1] = fmaf(xv, wa.y, acc[1]);
        acc[2] = fmaf(xv, wa.z, acc[2]);
        acc[3] = fmaf(xv, wa.w, acc[3]);
        acc[4] = fmaf(xv, wb.x, acc[4]);
        acc[5] = fmaf(xv, wb.y, acc[5]);
        acc[6] = fmaf(xv, wb.z, acc[6]);
        acc[7] = fmaf(xv, wb.w, acc[7]);
    }

    if (cpart != 0) {
#pragma unroll
        for (int s = 0; s < 8; s++) part[cpart - 1][w][s] = acc[s];
    }
    __syncthreads();

    if (cpart == 0) {
#pragma unroll
        for (int s = 0; s < 8; s++)
            acc[s] += part[0][w][s] + part[1][w][s] + part[2][w][s]
                    + __ldg(&bias[s]);

        // pixel shuffle: out (oy=2h+r1, ox=2w+r2) uses channels s=r1*2+r2
        // (x-coord) and 4+s (y-coord). Reference quirk: x-coord uses the
        // h-linspace evaluated at oy; y-coord uses w-linspace at ox.
#pragma unroll
        for (int s = 0; s < 4; s++) {
            int oy = 2 * h + (s >> 1);
            int ox = 2 * w + (s & 1);
            float gx = fmaf((float)oy, 2.0f / 127.0f, -1.0f) + acc[s];
            float gy = fmaf((float)ox, 2.0f / 127.0f, -1.0f) + acc[4 + s];
            // ix = ((g+1)*64 - 1)*0.5 = 32*g + 31.5
            float ix = fmaf(gx, 32.0f, 31.5f);
            float iy = fmaf(gy, 32.0f, 31.5f);
            g_coord[(b * OYn + oy) * OXn + ox] = make_float2(ix, iy);
        }
    }
}

// ---------------------------------------------------------------------------
// Stage 2: bilinear sample. Block = (b, quad of channels). Four 16 KB planes
// staged in SMEM interleaved as float4 (row pad 65): each corner gather is
// ONE LDS.128 serving 4 channels — LDS per-op floor amortized 4-wide.
// Each thread processes 2 adjacent pixels (LDG.128 coords, STG.64 stores).
// ---------------------------------------------------------------------------
__device__ __forceinline__ float4 bilin4(const float4* __restrict__ plane,
                                         float ix, float iy)
{
    float fx = floorf(ix);
    float fy = floorf(iy);
    int x0 = (int)fx;
    int y0 = (int)fy;
    float wx = ix - fx;
    float wy = iy - fy;

    float w00 = (1.0f - wy) * (1.0f - wx);
    float w01 = (1.0f - wy) * wx;
    float w10 = wy * (1.0f - wx);
    float w11 = wy * wx;

    // zeros padding: zero the weight of OOB corners, clamp the index
    if ((unsigned)x0       >= (unsigned)Wn) { w00 = 0.0f; w10 = 0.0f; }
    if ((unsigned)(x0 + 1) >= (unsigned)Wn) { w01 = 0.0f; w11 = 0.0f; }
    if ((unsigned)y0       >= (unsigned)Hn) { w00 = 0.0f; w01 = 0.0f; }
    if ((unsigned)(y0 + 1) >= (unsigned)Hn) { w10 = 0.0f; w11 = 0.0f; }

    int xc0 = min(max(x0, 0), Wn - 1);
    int xc1 = min(max(x0 + 1, 0), Wn - 1);
    int yc0 = min(max(y0, 0), Hn - 1);
    int yc1 = min(max(y0 + 1, 0), Hn - 1);

    float4 v00 = plane[yc0 * PADW + xc0];
    float4 v01 = plane[yc0 * PADW + xc1];
    float4 v10 = plane[yc1 * PADW + xc0];
    float4 v11 = plane[yc1 * PADW + xc1];

    float4 r;
    r.x = fmaf(v00.x, w00, fmaf(v01.x, w01, fmaf(v10.x, w10, v11.x * w11)));
    r.y = fmaf(v00.y, w00, fmaf(v01.y, w01, fmaf(v10.y, w10, v11.y * w11)));
    r.z = fmaf(v00.z, w00, fmaf(v01.z, w01, fmaf(v10.z, w10, v11.z * w11)));
    r.w = fmaf(v00.w, w00, fmaf(v01.w, w01, fmaf(v10.w, w10, v11.w * w11)));
    return r;
}

__global__ __launch_bounds__(256) void dysample_stage2(
    const float* __restrict__ x,
    float* __restrict__ out)
{
    extern __shared__ float4 plane[];     // 64*65 float4 = 66,560 B

    int bid = blockIdx.x;                 // 0..1023
    int b   = bid >> 6;                   // batch
    int cg  = bid & 63;                   // channel quad index

    const float* p0 = x + ((size_t)b * Cn + (size_t)cg * 4) * PLANE;

    // Stage 4 planes interleaved as float4 cells (coalesced LDG.128 reads).
    for (int i = threadIdx.x * 4; i < PLANE; i += 256 * 4) {
        float4 a = *reinterpret_cast<const float4*>(p0 + i);
        float4 c = *reinterpret_cast<const float4*>(p0 + PLANE + i);
        float4 d = *reinterpret_cast<const float4*>(p0 + 2 * PLANE + i);
        float4 e = *reinterpret_cast<const float4*>(p0 + 3 * PLANE + i);
        int row = i >> 6, col = i & 63;
        float4* dst = &plane[row * PADW + col];
        dst[0] = make_float4(a.x, c.x, d.x, e.x);
        dst[1] = make_float4(a.y, c.y, d.y, e.y);
        dst[2] = make_float4(a.z, c.z, d.z, e.z);
        dst[3] = make_float4(a.w, c.w, d.w, e.w);
    }
    __syncthreads();

    const float* cbase = (const float*)&g_coord[(size_t)b * OYn * OXn];
    float* o0 = out + ((size_t)b * Cn + (size_t)cg * 4) * (OYn * OXn);
    float* o1 = o0 + OYn * OXn;
    float* o2 = o1 + OYn * OXn;
    float* o3 = o2 + OYn * OXn;

    // 16384 pixels, 2 per thread -> 32 iterations
#pragma unroll 2
    for (int it = 0; it < 32; ++it) {
        int p = it * 512 + threadIdx.x * 2;
        float4 co = *reinterpret_cast<const float4*>(cbase + (size_t)p * 2);

        float4 r0 = bilin4(plane, co.x, co.y);
        float4 r1 = bilin4(plane, co.z, co.w);

        *reinterpret_cast<float2*>(o0 + p) = make_float2(r0.x, r1.x);
        *reinterpret_cast<float2*>(o1 + p) = make_float2(r0.y, r1.y);
        *reinterpret_cast<float2*>(o2 + p) = make_float2(r0.z, r1.z);
        *reinterpret_cast<float2*>(o3 + p) = make_float2(r0.w, r1.w);
    }
}

extern "C" void kernel_launch(void* const* d_in, const int* in_sizes, int n_in,
                              void* d_out, int out_size)
{
    const float* x      = (const float*)d_in[0];
    const float* weight = (const float*)d_in[1];
    const float* bias   = (const float*)d_in[2];
    float* out          = (float*)d_out;

    dysample_stage1<<<1024, 256>>>(x, weight, bias);   // 16*64 (b,h) rows

    const int smem2 = Hn * PADW * (int)sizeof(float4); // 66,560 B
    cudaFuncSetAttribute(dysample_stage2,
                         cudaFuncAttributeMaxDynamicSharedMemorySize, smem2);
    dysample_stage2<<<1024, 256, smem2>>>(x, out);     // 16*64 (b,ch-quad)
}

// round 5
// speedup vs baseline: 1.3714x; 1.3714x over previous
#include <cuda_runtime.h>
#include <cuda_fp16.h>

// Problem constants (fixed shapes):
//   x:      (16, 256, 64, 64)  fp32
//   weight: (8, 256)           fp32
//   bias:   (8,)               fp32
//   out:    (16, 256, 128, 128) fp32
#define Bn  16
#define Cn  256
#define Hn  64
#define Wn  64
#define OYn 128
#define OXn 128
#define PLANE (Hn * Wn)        // 4096
#define PADW 65                // padded row stride (uint2 cells)

// Per-output-pixel sampling coordinates (ix, iy). 16*128*128 float2 = 2 MB.
__device__ float2 g_coord[Bn * OYn * OXn];

// ---------------------------------------------------------------------------
// Stage 1: 1x1 conv (8 dots of length 256) + pixel shuffle + grid build.
// Block = one (b, h) row: 64 pixels x 4 channel-parts (64 ch each).
// ---------------------------------------------------------------------------
__global__ __launch_bounds__(256) void dysample_stage1(
    const float* __restrict__ x,
    const float* __restrict__ weight,
    const float* __restrict__ bias)
{
    __shared__ float wt[Cn * 8];          // transposed: wt[c*8+o]
    __shared__ float part[3][64][9];      // padded to 9 -> conflict-free

    for (int i = threadIdx.x; i < Cn * 8; i += 256)
        wt[(i & 255) * 8 + (i >> 8)] = weight[i];
    __syncthreads();

    int w     = threadIdx.x & 63;
    int cpart = threadIdx.x >> 6;         // 0..3
    int bh    = blockIdx.x;               // b*64 + h
    int b     = bh >> 6;
    int h     = bh & 63;

    const float* xb = x + ((size_t)b * Cn + cpart * 64) * PLANE + h * Wn + w;
    const float* wr0 = &wt[(cpart * 64) * 8];

    float acc[8];
#pragma unroll
    for (int s = 0; s < 8; s++) acc[s] = 0.0f;

#pragma unroll 8
    for (int c = 0; c < 64; ++c) {
        float xv = __ldg(xb + (size_t)c * PLANE);       // coalesced along w
        float4 wa = *reinterpret_cast<const float4*>(wr0 + c * 8);
        float4 wb = *reinterpret_cast<const float4*>(wr0 + c * 8 + 4);
        acc[0] = fmaf(xv, wa.x, acc[0]);
        acc[1] = fmaf(xv, wa.y, acc[1]);
        acc[2] = fmaf(xv, wa.z, acc[2]);
        acc[3] = fmaf(xv, wa.w, acc[3]);
        acc[4] = fmaf(xv, wb.x, acc[4]);
        acc[5] = fmaf(xv, wb.y, acc[5]);
        acc[6] = fmaf(xv, wb.z, acc[6]);
        acc[7] = fmaf(xv, wb.w, acc[7]);
    }

    if (cpart != 0) {
#pragma unroll
        for (int s = 0; s < 8; s++) part[cpart - 1][w][s] = acc[s];
    }
    __syncthreads();

    if (cpart == 0) {
#pragma unroll
        for (int s = 0; s < 8; s++)
            acc[s] += part[0][w][s] + part[1][w][s] + part[2][w][s]
                    + __ldg(&bias[s]);

        // pixel shuffle: out (oy=2h+r1, ox=2w+r2) uses channels s=r1*2+r2
        // (x-coord) and 4+s (y-coord). Reference quirk: x-coord uses the
        // h-linspace evaluated at oy; y-coord uses w-linspace at ox.
#pragma unroll
        for (int s = 0; s < 4; s++) {
            int oy = 2 * h + (s >> 1);
            int ox = 2 * w + (s & 1);
            float gx = fmaf((float)oy, 2.0f / 127.0f, -1.0f) + acc[s];
            float gy = fmaf((float)ox, 2.0f / 127.0f, -1.0f) + acc[4 + s];
            // ix = ((g+1)*64 - 1)*0.5 = 32*g + 31.5
            float ix = fmaf(gx, 32.0f, 31.5f);
            float iy = fmaf(gy, 32.0f, 31.5f);
            g_coord[(b * OYn + oy) * OXn + ox] = make_float2(ix, iy);
        }
    }
}

// ---------------------------------------------------------------------------
// Stage 2: bilinear sample. Block = (b, quad of channels). Four planes are
// staged in SMEM as fp16 packed 4-wide per cell (uint2 = 8 B): halves the
// bytes per output through the LDS crossbar (the measured bottleneck) while
// keeping SMEM at 33.3 KB -> 6 blocks/SM (75% occupancy).
// Accumulation stays fp32; only the staged storage is fp16.
// ---------------------------------------------------------------------------
__device__ __forceinline__ uint2 packh4(float a, float b, float c, float d)
{
    __half2 lo = __floats2half2_rn(a, b);
    __half2 hi = __floats2half2_rn(c, d);
    uint2 r;
    r.x = *reinterpret_cast<unsigned int*>(&lo);
    r.y = *reinterpret_cast<unsigned int*>(&hi);
    return r;
}

__device__ __forceinline__ void unpack4(uint2 v, float2& p01, float2& p23)
{
    p01 = __half22float2(*reinterpret_cast<const __half2*>(&v.x));
    p23 = __half22float2(*reinterpret_cast<const __half2*>(&v.y));
}

__device__ __forceinline__ float4 bilin4h(const uint2* __restrict__ plane,
                                          float ix, float iy)
{
    float fx = floorf(ix);
    float fy = floorf(iy);
    int x0 = (int)fx;
    int y0 = (int)fy;
    float wx = ix - fx;
    float wy = iy - fy;

    float w00 = (1.0f - wy) * (1.0f - wx);
    float w01 = (1.0f - wy) * wx;
    float w10 = wy * (1.0f - wx);
    float w11 = wy * wx;

    // zeros padding: zero the weight of OOB corners, clamp the index
    if ((unsigned)x0       >= (unsigned)Wn) { w00 = 0.0f; w10 = 0.0f; }
    if ((unsigned)(x0 + 1) >= (unsigned)Wn) { w01 = 0.0f; w11 = 0.0f; }
    if ((unsigned)y0       >= (unsigned)Hn) { w00 = 0.0f; w01 = 0.0f; }
    if ((unsigned)(y0 + 1) >= (unsigned)Hn) { w10 = 0.0f; w11 = 0.0f; }

    int xc0 = min(max(x0, 0), Wn - 1);
    int xc1 = min(max(x0 + 1, 0), Wn - 1);
    int yc0 = min(max(y0, 0), Hn - 1);
    int yc1 = min(max(y0 + 1, 0), Hn - 1);

    uint2 v00 = plane[yc0 * PADW + xc0];
    uint2 v01 = plane[yc0 * PADW + xc1];
    uint2 v10 = plane[yc1 * PADW + xc0];
    uint2 v11 = plane[yc1 * PADW + xc1];

    float2 a01, a23, b01, b23;
    unpack4(v00, a01, a23);
    unpack4(v01, b01, b23);
    float rx = a01.x * w00 + b01.x * w01;
    float ry = a01.y * w00 + b01.y * w01;
    float rz = a23.x * w00 + b23.x * w01;
    float rw = a23.y * w00 + b23.y * w01;
    unpack4(v10, a01, a23);
    unpack4(v11, b01, b23);
    rx = fmaf(a01.x, w10, fmaf(b01.x, w11, rx));
    ry = fmaf(a01.y, w10, fmaf(b01.y, w11, ry));
    rz = fmaf(a23.x, w10, fmaf(b23.x, w11, rz));
    rw = fmaf(a23.y, w10, fmaf(b23.y, w11, rw));
    return make_float4(rx, ry, rz, rw);
}

__global__ __launch_bounds__(256, 6) void dysample_stage2(
    const float* __restrict__ x,
    float* __restrict__ out)
{
    __shared__ uint2 plane[Hn * PADW];    // 64*65*8 = 33,280 B

    int bid = blockIdx.x;                 // 0..1023
    int b   = bid >> 6;                   // batch
    int cg  = bid & 63;                   // channel quad index

    const float* p0 = x + ((size_t)b * Cn + (size_t)cg * 4) * PLANE;

    // Stage 4 planes as fp16x4 cells (coalesced LDG.128 reads).
    for (int i = threadIdx.x * 4; i < PLANE; i += 256 * 4) {
        float4 a = *reinterpret_cast<const float4*>(p0 + i);
        float4 c = *reinterpret_cast<const float4*>(p0 + PLANE + i);
        float4 d = *reinterpret_cast<const float4*>(p0 + 2 * PLANE + i);
        float4 e = *reinterpret_cast<const float4*>(p0 + 3 * PLANE + i);
        int row = i >> 6, col = i & 63;
        uint2* dst = &plane[row * PADW + col];
        dst[0] = packh4(a.x, c.x, d.x, e.x);
        dst[1] = packh4(a.y, c.y, d.y, e.y);
        dst[2] = packh4(a.z, c.z, d.z, e.z);
        dst[3] = packh4(a.w, c.w, d.w, e.w);
    }
    __syncthreads();

    const float* cbase = (const float*)&g_coord[(size_t)b * OYn * OXn];
    float* o0 = out + ((size_t)b * Cn + (size_t)cg * 4) * (OYn * OXn);
    float* o1 = o0 + OYn * OXn;
    float* o2 = o1 + OYn * OXn;
    float* o3 = o2 + OYn * OXn;

    // 16384 pixels, 2 per thread -> 32 iterations
#pragma unroll 2
    for (int it = 0; it < 32; ++it) {
        int p = it * 512 + threadIdx.x * 2;
        float4 co = *reinterpret_cast<const float4*>(cbase + (size_t)p * 2);

        float4 r0 = bilin4h(plane, co.x, co.y);
        float4 r1 = bilin4h(plane, co.z, co.w);

        *reinterpret_cast<float2*>(o0 + p) = make_float2(r0.x, r1.x);
        *reinterpret_cast<float2*>(o1 + p) = make_float2(r0.y, r1.y);
        *reinterpret_cast<float2*>(o2 + p) = make_float2(r0.z, r1.z);
        *reinterpret_cast<float2*>(o3 + p) = make_float2(r0.w, r1.w);
    }
}

extern "C" void kernel_launch(void* const* d_in, const int* in_sizes, int n_in,
                              void* d_out, int out_size)
{
    const float* x      = (const float*)d_in[0];
    const float* weight = (const float*)d_in[1];
    const float* bias   = (const float*)d_in[2];
    float* out          = (float*)d_out;

    dysample_stage1<<<1024, 256>>>(x, weight, bias);   // 16*64 (b,h) rows
    dysample_stage2<<<1024, 256>>>(x, out);            // 16*64 (b,ch-quad)
}